// round 13
// baseline (speedup 1.0000x reference)
#include <cuda_runtime.h>
#include <cstddef>
#include <cstdint>

// ---------------------------------------------------------------------------
// MultiHeadedAttentionWithCache  (B=16,Q=16,D=1024,H=16,DH=64,C=4096,KLEN=4112)
// d_out = concat(out[16,16,1024], k_up[16,16,4112,64], v_up[16,16,4112,64])
// ---------------------------------------------------------------------------

#define Bdim 16
#define Qdim 16
#define Ddim 1024
#define Hdim 16
#define DH   64
#define Cdim 4096
#define KLEN 4112
#define ROWS 256
#define NSPLIT 8
#define KS 4

__device__ float  g_q_heads[ROWS * Ddim];
__device__ float  g_attn_x[ROWS * Ddim];
__device__ float  g_part_acc[256 * NSPLIT * Qdim * DH];
__device__ float2 g_part_ml[256 * NSPLIT * Qdim];
__device__ float  g_proj_part[3 * KS * ROWS * Ddim];

// ---------------------------------------------------------------------------
// Projection GEMM, split-K
// ---------------------------------------------------------------------------
#define BM 64
#define BN 64
#define BK 16

__global__ void __launch_bounds__(256)
proj_kernel(const float* __restrict__ Aq, const float* __restrict__ Ak,
            const float* __restrict__ Av,
            const float* __restrict__ Wq, const float* __restrict__ Wk,
            const float* __restrict__ Wv,
            int mode_base)
{
    const int zz = blockIdx.z;
    const int m  = mode_base ? 3 : (zz / KS);
    const int ks = mode_base ? zz : (zz % KS);
    const int mslot = (m == 3) ? 0 : m;

    const float* A = (m == 0) ? Aq : (m == 1) ? Ak : (m == 2) ? Av : g_attn_x;
    const float* W = (m == 1) ? Wk : (m == 2) ? Wv : Wq;

    __shared__ float As[BK][BM + 4];
    __shared__ float Bs[BK][BN];

    const int rowBase = blockIdx.x * BM;
    const int colBase = blockIdx.y * BN;

    const int t  = threadIdx.x;
    const int tx = t & 15;
    const int ty = t >> 4;

    float acc[4][4];
#pragma unroll
    for (int i = 0; i < 4; i++)
#pragma unroll
        for (int j = 0; j < 4; j++) acc[i][j] = 0.f;

    const int la_r  = t & 63;
    const int la_k4 = (t >> 6) * 4;
    const int lb_k  = t >> 4;
    const int lb_c4 = (t & 15) * 4;

    const int k0 = ks * (Ddim / KS);

    for (int kt = k0; kt < k0 + Ddim / KS; kt += BK) {
        float4 a4 = *(const float4*)&A[(size_t)(rowBase + la_r) * Ddim + kt + la_k4];
        As[la_k4 + 0][la_r] = a4.x;
        As[la_k4 + 1][la_r] = a4.y;
        As[la_k4 + 2][la_r] = a4.z;
        As[la_k4 + 3][la_r] = a4.w;
        *(float4*)&Bs[lb_k][lb_c4] =
            *(const float4*)&W[(size_t)(kt + lb_k) * Ddim + colBase + lb_c4];
        __syncthreads();
#pragma unroll
        for (int kk = 0; kk < BK; kk++) {
            float ar[4], br[4];
            *(float4*)ar = *(const float4*)&As[kk][ty * 4];
            *(float4*)br = *(const float4*)&Bs[kk][tx * 4];
#pragma unroll
            for (int i = 0; i < 4; i++)
#pragma unroll
                for (int j = 0; j < 4; j++)
                    acc[i][j] += ar[i] * br[j];
        }
        __syncthreads();
    }

    float* P = g_proj_part + (size_t)(mslot * KS + ks) * ROWS * Ddim;
#pragma unroll
    for (int i = 0; i < 4; i++) {
        const int row = rowBase + ty * 4 + i;
        float4 v = make_float4(acc[i][0], acc[i][1], acc[i][2], acc[i][3]);
        *(float4*)&P[(size_t)row * Ddim + colBase + tx * 4] = v;
    }
}

// ---------------------------------------------------------------------------
// Combine split-K proj partials + bias + scatter
// ---------------------------------------------------------------------------
__device__ __forceinline__ void combine_proj_body(
    const float* __restrict__ bias_in,
    float* __restrict__ out,
    float* __restrict__ k_up, float* __restrict__ v_up,
    int m, int row, int t)
{
    const int mslot = (m == 3) ? 0 : m;
    const int col = t * 4;

    const float* P = g_proj_part + (size_t)(mslot * KS) * ROWS * Ddim
                   + (size_t)row * Ddim + col;
    float4 s = *(const float4*)&P[0];
#pragma unroll
    for (int ksl = 1; ksl < KS; ksl++) {
        float4 p = *(const float4*)&P[(size_t)ksl * ROWS * Ddim];
        s.x += p.x; s.y += p.y; s.z += p.z; s.w += p.w;
    }
    float4 bb = *(const float4*)&bias_in[col];
    s.x += bb.x; s.y += bb.y; s.z += bb.z; s.w += bb.w;

    const int b  = row >> 4;
    const int qi = row & 15;
    const int h  = col >> 6;
    const int dh = col & 63;

    if (m == 0) {
        *(float4*)&g_q_heads[(size_t)((b * Hdim + h) * Qdim + qi) * DH + dh] = s;
    } else if (m == 1) {
        *(float4*)&k_up[((size_t)(b * Hdim + h) * KLEN + Cdim + qi) * DH + dh] = s;
    } else if (m == 2) {
        *(float4*)&v_up[((size_t)(b * Hdim + h) * KLEN + Cdim + qi) * DH + dh] = s;
    } else {
        *(float4*)&out[(size_t)row * Ddim + col] = s;
    }
}

__global__ void __launch_bounds__(256)
combine_proj(const float* __restrict__ bias_in,
             float* __restrict__ out,
             float* __restrict__ k_up, float* __restrict__ v_up,
             int m)
{
    combine_proj_body(bias_in, out, k_up, v_up, m, blockIdx.x, threadIdx.x);
}

__global__ void __launch_bounds__(256)
combine_proj_kv(const float* __restrict__ bk, const float* __restrict__ bv,
                float* __restrict__ k_up, float* __restrict__ v_up)
{
    const int m = 1 + (int)blockIdx.y;
    combine_proj_body((m == 1) ? bk : bv, nullptr, k_up, v_up, m,
                      blockIdx.x, threadIdx.x);
}

// ---------------------------------------------------------------------------
// cp.async helpers
// ---------------------------------------------------------------------------
__device__ __forceinline__ void cp_async16(unsigned int smem_addr, const void* gptr) {
    asm volatile("cp.async.cg.shared.global [%0], [%1], 16;\n"
                 :: "r"(smem_addr), "l"(gptr) : "memory");
}
__device__ __forceinline__ void cp_commit() {
    asm volatile("cp.async.commit_group;\n" ::: "memory");
}
__device__ __forceinline__ void cp_wait1() {
    asm volatile("cp.async.wait_group 1;\n" ::: "memory");
}

// ---------------------------------------------------------------------------
// Split-K fused attention + cache copy — L1tex-byte-optimized.
// Scores: thread owns 2 K rows (lj, lj+32), 8-float kk slice; Q LDS reused
//         across both rows; 8-lane shfl reduce. Ss layout [q][j].
// PV: thread = (js, q-pair, dh-quad); P via LDS.128; V read once per 2 q.
// Mask: int4; softmax vectorized LDS/STS.128.
// ---------------------------------------------------------------------------
__global__ void __launch_bounds__(256, 4)
attn_kernel(const float* __restrict__ cache_k, const float* __restrict__ cache_v,
            const int* __restrict__ mask,
            float* __restrict__ k_up, float* __restrict__ v_up)
{
    const int blk   = blockIdx.x;
    const int bh    = blk >> 3;
    const int split = blk & 7;
    const int b     = bh >> 4;

    __shared__ float Qst[16][68];      // [q][kk] pre-scaled by 1/8
    __shared__ float Vs[2][64][68];    // double-buffered V chunk [j][dh]
    __shared__ float Ss[16][68];       // [q][j] scores -> probabilities
    __shared__ float s_corr[16];
    __shared__ float s_red[128][8];

    const int t = threadIdx.x;

    for (int i = t; i < Qdim * DH; i += 256) {
        const int q  = i >> 6;
        const int kk = i & 63;
        Qst[q][kk] = g_q_heads[(size_t)(bh * Qdim + q) * DH + kk] * 0.125f;
    }

    const int lj = t >> 3;           // 0..31 : K/V rows lj and lj+32
    const int gg = t & 7;            // kk slice: gg*4 and gg*4+32

    const int row = t >> 4;          // softmax role: query row
    const int j4  = (t & 15) * 4;    // softmax role: 4 j's

    const int js  = t >> 7;          // PV: j half
    const int qg  = (t >> 4) & 7;    // PV: query pair
    const int dh4 = t & 15;          // PV: dh quad

    float m_i = -1e30f, l_i = 0.f;
    // acc0,acc1 = query q0 dh[dh4*4..+3]; acc2,acc3 = query q1
    unsigned long long a0 = 0ull, a1 = 0ull, a2 = 0ull, a3 = 0ull;

    const float* Kb = cache_k + (size_t)bh * Cdim * DH;
    const float* Vb = cache_v + (size_t)bh * Cdim * DH;
    float* Kout = k_up + (size_t)bh * KLEN * DH;
    float* Vout = v_up + (size_t)bh * KLEN * DH;
    const int* Mb = mask + (size_t)b * Qdim * KLEN;

    float4 kf[4];    // [row r][slice e]: kf[r*2+e]
    int4 mcur, mnext;
    int cur = 0;

    auto prefetch_k = [&](int c) {
        if (c < 64) {
            const float* p0 = &Kb[((size_t)(c * 64 + lj)) * DH + gg * 4];
            kf[0] = *(const float4*)p0;
            kf[1] = *(const float4*)(p0 + 32);
            const float* p1 = p0 + 32 * DH;
            kf[2] = *(const float4*)p1;
            kf[3] = *(const float4*)(p1 + 32);
        } else {
            const float4 z = make_float4(0.f, 0.f, 0.f, 0.f);
            if (lj < 16) {
                const float* p0 = &Kout[((size_t)(Cdim + lj)) * DH + gg * 4];
                kf[0] = *(const float4*)p0;
                kf[1] = *(const float4*)(p0 + 32);
            } else { kf[0] = z; kf[1] = z; }
            kf[2] = z; kf[3] = z;
        }
    };

    auto prefetch_mask = [&](int c, int4& mr) {
        if (c < 64 || j4 < 16)
            mr = *(const int4*)&Mb[row * KLEN + c * 64 + j4];
        else
            mr = make_int4(0, 0, 0, 0);
    };

    auto issue_v = [&](int c, int buf) {
        if (c < 64) {
            const float* p0 = &Vb[((size_t)(c * 64 + lj)) * DH + gg * 4];
            cp_async16((unsigned int)__cvta_generic_to_shared(&Vs[buf][lj][gg * 4]), p0);
            cp_async16((unsigned int)__cvta_generic_to_shared(&Vs[buf][lj][gg * 4 + 32]), p0 + 32);
            const float* p1 = p0 + 32 * DH;
            cp_async16((unsigned int)__cvta_generic_to_shared(&Vs[buf][lj + 32][gg * 4]), p1);
            cp_async16((unsigned int)__cvta_generic_to_shared(&Vs[buf][lj + 32][gg * 4 + 32]), p1 + 32);
        } else if (c == 64) {
            const float4 z = make_float4(0.f, 0.f, 0.f, 0.f);
            if (lj < 16) {
                const float* p0 = &Vout[((size_t)(Cdim + lj)) * DH + gg * 4];
                cp_async16((unsigned int)__cvta_generic_to_shared(&Vs[buf][lj][gg * 4]), p0);
                cp_async16((unsigned int)__cvta_generic_to_shared(&Vs[buf][lj][gg * 4 + 32]), p0 + 32);
            } else {
                *(float4*)&Vs[buf][lj][gg * 4] = z;
                *(float4*)&Vs[buf][lj][gg * 4 + 32] = z;
            }
            *(float4*)&Vs[buf][lj + 32][gg * 4] = z;
            *(float4*)&Vs[buf][lj + 32][gg * 4 + 32] = z;
        }
        cp_commit();
    };

    prefetch_k(split);
    prefetch_mask(split, mcur);
    issue_v(split, 0);

    for (int c = split; c < 65; c += NSPLIT) {
        const int kvBase = c * 64;
        const bool full  = (c < 64);

        __syncthreads();   // prev PV done; Vs[cur^1] free; Ss writable

        // K cache copy (from registers)
        if (full) {
            float* d0 = &Kout[((size_t)(kvBase + lj)) * DH + gg * 4];
            *(float4*)d0 = kf[0];
            *(float4*)(d0 + 32) = kf[1];
            float* d1 = d0 + 32 * DH;
            *(float4*)d1 = kf[2];
            *(float4*)(d1 + 32) = kf[3];
        }

        // start V load for next chunk into other buffer
        issue_v(c + NSPLIT, cur ^ 1);

        // --- scores: 2 passes of 8 queries, 2 K rows per thread ---
#pragma unroll
        for (int p = 0; p < 2; p++) {
            float s[16];
#pragma unroll
            for (int i = 0; i < 16; i++) s[i] = 0.f;
#pragma unroll
            for (int e = 0; e < 2; e++) {
                const float4 k0 = kf[e];
                const float4 k1 = kf[2 + e];
#pragma unroll
                for (int ql = 0; ql < 8; ql++) {
                    float4 qv = *(const float4*)&Qst[p * 8 + ql][gg * 4 + e * 32];
                    s[ql * 2 + 0] += qv.x * k0.x + qv.y * k0.y + qv.z * k0.z + qv.w * k0.w;
                    s[ql * 2 + 1] += qv.x * k1.x + qv.y * k1.y + qv.z * k1.z + qv.w * k1.w;
                }
            }
#pragma unroll
            for (int off = 1; off <= 4; off <<= 1)
#pragma unroll
                for (int i = 0; i < 16; i++)
                    s[i] += __shfl_xor_sync(0xffffffffu, s[i], off);
            // lane gg keeps query p*8+gg
            Ss[p * 8 + gg][lj]      = s[gg * 2 + 0];
            Ss[p * 8 + gg][lj + 32] = s[gg * 2 + 1];
        }

        // prefetch K + mask for next chunk
        if (c + NSPLIT < 65) {
            prefetch_k(c + NSPLIT);
            prefetch_mask(c + NSPLIT, mnext);
        }

        __syncthreads();   // Ss scores ready

        // --- online softmax (vectorized) ---
        {
            float4 sv = *(const float4*)&Ss[row][j4];
            if (mcur.x == 0) sv.x = -1e9f;
            if (mcur.y == 0) sv.y = -1e9f;
            if (mcur.z == 0) sv.z = -1e9f;
            if (mcur.w == 0) sv.w = -1e9f;
            float mx = fmaxf(fmaxf(sv.x, sv.y), fmaxf(sv.z, sv.w));
#pragma unroll
            for (int off = 8; off; off >>= 1)
                mx = fmaxf(mx, __shfl_xor_sync(0xffffffffu, mx, off));
            const float m_new = fmaxf(m_i, mx);
            const float corr  = __expf(m_i - m_new);
            float4 pv;
            pv.x = __expf(sv.x - m_new);
            pv.y = __expf(sv.y - m_new);
            pv.z = __expf(sv.z - m_new);
            pv.w = __expf(sv.w - m_new);
            *(float4*)&Ss[row][j4] = pv;
            float lsum = pv.x + pv.y + pv.z + pv.w;
#pragma unroll
            for (int off = 8; off; off >>= 1)
                lsum += __shfl_xor_sync(0xffffffffu, lsum, off);
            l_i = l_i * corr + lsum;
            m_i = m_new;
            if ((t & 15) == 0) s_corr[row] = corr;
        }

        cp_wait1();        // current chunk's V resident
        __syncthreads();   // probs + corr + Vs[cur] visible

        // --- uniform V cache copy ---
        if (full) {
            float* d0 = &Vout[((size_t)(kvBase + lj)) * DH + gg * 4];
            *(float4*)d0        = *(const float4*)&Vs[cur][lj][gg * 4];
            *(float4*)(d0 + 32) = *(const float4*)&Vs[cur][lj][gg * 4 + 32];
            float* d1 = d0 + 32 * DH;
            *(float4*)d1        = *(const float4*)&Vs[cur][lj + 32][gg * 4];
            *(float4*)(d1 + 32) = *(const float4*)&Vs[cur][lj + 32][gg * 4 + 32];
        }

        // --- PV: (js, q-pair qg, dh-quad dh4) ---
        {
            const int q0 = qg * 2;
            const float c0 = s_corr[q0];
            const float c1 = s_corr[q0 + 1];
            unsigned long long cc0, cc1;
            asm("mov.b64 %0, {%1, %1};" : "=l"(cc0) : "f"(c0));
            asm("mov.b64 %0, {%1, %1};" : "=l"(cc1) : "f"(c1));
            asm("mul.rn.f32x2 %0, %0, %1;" : "+l"(a0) : "l"(cc0));
            asm("mul.rn.f32x2 %0, %0, %1;" : "+l"(a1) : "l"(cc0));
            asm("mul.rn.f32x2 %0, %0, %1;" : "+l"(a2) : "l"(cc1));
            asm("mul.rn.f32x2 %0, %0, %1;" : "+l"(a3) : "l"(cc1));
            const int jBase = js * 32;
#pragma unroll 4
            for (int j = jBase; j < jBase + 32; j += 4) {
                float4 p0 = *(const float4*)&Ss[q0][j];
                float4 p1 = *(const float4*)&Ss[q0 + 1][j];
                float pa0[4] = {p0.x, p0.y, p0.z, p0.w};
                float pa1[4] = {p1.x, p1.y, p1.z, p1.w};
#pragma unroll
                for (int u = 0; u < 4; u++) {
                    ulonglong2 vv = *reinterpret_cast<const ulonglong2*>(&Vs[cur][j + u][dh4 * 4]);
                    unsigned long long pp0, pp1;
                    asm("mov.b64 %0, {%1, %1};" : "=l"(pp0) : "f"(pa0[u]));
                    asm("mov.b64 %0, {%1, %1};" : "=l"(pp1) : "f"(pa1[u]));
                    asm("fma.rn.f32x2 %0, %1, %2, %0;" : "+l"(a0) : "l"(vv.x), "l"(pp0));
                    asm("fma.rn.f32x2 %0, %1, %2, %0;" : "+l"(a1) : "l"(vv.y), "l"(pp0));
                    asm("fma.rn.f32x2 %0, %1, %2, %0;" : "+l"(a2) : "l"(vv.x), "l"(pp1));
                    asm("fma.rn.f32x2 %0, %1, %2, %0;" : "+l"(a3) : "l"(vv.y), "l"(pp1));
                }
            }
        }

        mcur = mnext;
        cur ^= 1;
    }

    if ((t & 15) == 0)
        g_part_ml[(bh * NSPLIT + split) * Qdim + row] = make_float2(m_i, l_i);

    float f0, f1, f2, f3, f4, f5, f6, f7;
    asm("mov.b64 {%0, %1}, %2;" : "=f"(f0), "=f"(f1) : "l"(a0));
    asm("mov.b64 {%0, %1}, %2;" : "=f"(f2), "=f"(f3) : "l"(a1));
    asm("mov.b64 {%0, %1}, %2;" : "=f"(f4), "=f"(f5) : "l"(a2));
    asm("mov.b64 {%0, %1}, %2;" : "=f"(f6), "=f"(f7) : "l"(a3));

    if (js == 1) {
        float* r = s_red[t - 128];
        r[0] = f0; r[1] = f1; r[2] = f2; r[3] = f3;
        r[4] = f4; r[5] = f5; r[6] = f6; r[7] = f7;
    }
    __syncthreads();
    if (js == 0) {
        const float* r = s_red[t];
        const int q0 = qg * 2;
        const size_t base = ((size_t)(bh * NSPLIT + split) * Qdim) * DH;
        float4 o0 = make_float4(f0 + r[0], f1 + r[1], f2 + r[2], f3 + r[3]);
        float4 o1 = make_float4(f4 + r[4], f5 + r[5], f6 + r[6], f7 + r[7]);
        *(float4*)&g_part_acc[base + (size_t)q0 * DH + dh4 * 4]       = o0;
        *(float4*)&g_part_acc[base + (size_t)(q0 + 1) * DH + dh4 * 4] = o1;
    }
}

// ---------------------------------------------------------------------------
// Combine attention split partials -> g_attn_x
// ---------------------------------------------------------------------------
__global__ void __launch_bounds__(256)
combine_kernel()
{
    const int bh  = blockIdx.x;
    const int t   = threadIdx.x;
    const int row = t >> 4;
    const int dh0 = (t & 15) * 4;

    float2 ml[NSPLIT];
    float m = -1e30f;
#pragma unroll
    for (int s = 0; s < NSPLIT; s++) {
        ml[s] = g_part_ml[(bh * NSPLIT + s) * Qdim + row];
        m = fmaxf(m, ml[s].x);
    }
    float l = 0.f;
    float4 o = make_float4(0.f, 0.f, 0.f, 0.f);
#pragma unroll
    for (int s = 0; s < NSPLIT; s++) {
        const float w = __expf(ml[s].x - m);
        l += ml[s].y * w;
        float4 a = *(const float4*)&g_part_acc[((size_t)(bh * NSPLIT + s) * Qdim + row) * DH + dh0];
        o.x += a.x * w; o.y += a.y * w; o.z += a.z * w; o.w += a.w * w;
    }
    const float inv = 1.f / l;
    const int b = bh >> 4;
    const int h = bh & 15;
    o.x *= inv; o.y *= inv; o.z *= inv; o.w *= inv;
    *(float4*)&g_attn_x[(size_t)(b * Qdim + row) * Ddim + h * DH + dh0] = o;
}

// ---------------------------------------------------------------------------
extern "C" void kernel_launch(void* const* d_in, const int* in_sizes, int n_in,
                              void* d_out, int out_size)
{
    const float* query   = (const float*)d_in[0];
    const float* key     = (const float*)d_in[1];
    const float* value   = (const float*)d_in[2];
    const int*   mask    = (const int*)d_in[3];
    const float* cache_k = (const float*)d_in[4];
    const float* cache_v = (const float*)d_in[5];
    const float* Wq = (const float*)d_in[6];
    const float* bq = (const float*)d_in[7];
    const float* Wk = (const float*)d_in[8];
    const float* bk = (const float*)d_in[9];
    const float* Wv = (const float*)d_in[10];
    const float* bv = (const float*)d_in[11];
    const float* Wo = (const float*)d_in[12];
    const float* bo = (const float*)d_in[13];

    float* out  = (float*)d_out;
    float* k_up = out + (size_t)Bdim * Qdim * Ddim;
    float* v_up = k_up + (size_t)Bdim * Hdim * KLEN * DH;

    // launches 1-3 (attn_kernel is the 4th launch — ncu hits #4)
    proj_kernel<<<dim3(4, 16, 3 * KS), 256>>>(query, key, value, Wq, Wk, Wv, 0);
    combine_proj<<<ROWS, 256>>>(bq, out, k_up, v_up, 0);
    combine_proj_kv<<<dim3(ROWS, 2), 256>>>(bk, bv, k_up, v_up);

    // 4: attention
    attn_kernel<<<Bdim * Hdim * NSPLIT, 256>>>(cache_k, cache_v, mask, k_up, v_up);

    combine_kernel<<<Bdim * Hdim, 256>>>();

    proj_kernel<<<dim3(4, 16, KS), 256>>>(nullptr, nullptr, nullptr, Wo, nullptr, nullptr, 1);
    combine_proj<<<ROWS, 256>>>(bo, out, k_up, v_up, 3);
}

// round 15
// speedup vs baseline: 1.0008x; 1.0008x over previous
#include <cuda_runtime.h>
#include <cstddef>
#include <cstdint>

// ---------------------------------------------------------------------------
// MultiHeadedAttentionWithCache  (B=16,Q=16,D=1024,H=16,DH=64,C=4096,KLEN=4112)
// d_out = concat(out[16,16,1024], k_up[16,16,4112,64], v_up[16,16,4112,64])
// ---------------------------------------------------------------------------

#define Bdim 16
#define Qdim 16
#define Ddim 1024
#define Hdim 16
#define DH   64
#define Cdim 4096
#define KLEN 4112
#define ROWS 256
#define NSPLIT 8
#define KS 4

__device__ float  g_q_heads[ROWS * Ddim];
__device__ float  g_attn_x[ROWS * Ddim];
__device__ float  g_part_acc[256 * NSPLIT * Qdim * DH];
__device__ float2 g_part_ml[256 * NSPLIT * Qdim];
__device__ float  g_proj_part[3 * KS * ROWS * Ddim];

// ---------------------------------------------------------------------------
// Projection GEMM, split-K
// ---------------------------------------------------------------------------
#define BM 64
#define BN 64
#define BK 16

__global__ void __launch_bounds__(256)
proj_kernel(const float* __restrict__ Aq, const float* __restrict__ Ak,
            const float* __restrict__ Av,
            const float* __restrict__ Wq, const float* __restrict__ Wk,
            const float* __restrict__ Wv,
            int mode_base)
{
    const int zz = blockIdx.z;
    const int m  = mode_base ? 3 : (zz / KS);
    const int ks = mode_base ? zz : (zz % KS);
    const int mslot = (m == 3) ? 0 : m;

    const float* A = (m == 0) ? Aq : (m == 1) ? Ak : (m == 2) ? Av : g_attn_x;
    const float* W = (m == 1) ? Wk : (m == 2) ? Wv : Wq;

    __shared__ float As[BK][BM + 4];
    __shared__ float Bs[BK][BN];

    const int rowBase = blockIdx.x * BM;
    const int colBase = blockIdx.y * BN;

    const int t  = threadIdx.x;
    const int tx = t & 15;
    const int ty = t >> 4;

    float acc[4][4];
#pragma unroll
    for (int i = 0; i < 4; i++)
#pragma unroll
        for (int j = 0; j < 4; j++) acc[i][j] = 0.f;

    const int la_r  = t & 63;
    const int la_k4 = (t >> 6) * 4;
    const int lb_k  = t >> 4;
    const int lb_c4 = (t & 15) * 4;

    const int k0 = ks * (Ddim / KS);

    for (int kt = k0; kt < k0 + Ddim / KS; kt += BK) {
        float4 a4 = *(const float4*)&A[(size_t)(rowBase + la_r) * Ddim + kt + la_k4];
        As[la_k4 + 0][la_r] = a4.x;
        As[la_k4 + 1][la_r] = a4.y;
        As[la_k4 + 2][la_r] = a4.z;
        As[la_k4 + 3][la_r] = a4.w;
        *(float4*)&Bs[lb_k][lb_c4] =
            *(const float4*)&W[(size_t)(kt + lb_k) * Ddim + colBase + lb_c4];
        __syncthreads();
#pragma unroll
        for (int kk = 0; kk < BK; kk++) {
            float ar[4], br[4];
            *(float4*)ar = *(const float4*)&As[kk][ty * 4];
            *(float4*)br = *(const float4*)&Bs[kk][tx * 4];
#pragma unroll
            for (int i = 0; i < 4; i++)
#pragma unroll
                for (int j = 0; j < 4; j++)
                    acc[i][j] += ar[i] * br[j];
        }
        __syncthreads();
    }

    float* P = g_proj_part + (size_t)(mslot * KS + ks) * ROWS * Ddim;
#pragma unroll
    for (int i = 0; i < 4; i++) {
        const int row = rowBase + ty * 4 + i;
        float4 v = make_float4(acc[i][0], acc[i][1], acc[i][2], acc[i][3]);
        *(float4*)&P[(size_t)row * Ddim + colBase + tx * 4] = v;
    }
}

// ---------------------------------------------------------------------------
// Combine split-K proj partials + bias + scatter
// ---------------------------------------------------------------------------
__device__ __forceinline__ void combine_proj_body(
    const float* __restrict__ bias_in,
    float* __restrict__ out,
    float* __restrict__ k_up, float* __restrict__ v_up,
    int m, int row, int t)
{
    const int mslot = (m == 3) ? 0 : m;
    const int col = t * 4;

    const float* P = g_proj_part + (size_t)(mslot * KS) * ROWS * Ddim
                   + (size_t)row * Ddim + col;
    float4 s = *(const float4*)&P[0];
#pragma unroll
    for (int ksl = 1; ksl < KS; ksl++) {
        float4 p = *(const float4*)&P[(size_t)ksl * ROWS * Ddim];
        s.x += p.x; s.y += p.y; s.z += p.z; s.w += p.w;
    }
    float4 bb = *(const float4*)&bias_in[col];
    s.x += bb.x; s.y += bb.y; s.z += bb.z; s.w += bb.w;

    const int b  = row >> 4;
    const int qi = row & 15;
    const int h  = col >> 6;
    const int dh = col & 63;

    if (m == 0) {
        *(float4*)&g_q_heads[(size_t)((b * Hdim + h) * Qdim + qi) * DH + dh] = s;
    } else if (m == 1) {
        *(float4*)&k_up[((size_t)(b * Hdim + h) * KLEN + Cdim + qi) * DH + dh] = s;
    } else if (m == 2) {
        *(float4*)&v_up[((size_t)(b * Hdim + h) * KLEN + Cdim + qi) * DH + dh] = s;
    } else {
        *(float4*)&out[(size_t)row * Ddim + col] = s;
    }
}

__global__ void __launch_bounds__(256)
combine_proj(const float* __restrict__ bias_in,
             float* __restrict__ out,
             float* __restrict__ k_up, float* __restrict__ v_up,
             int m)
{
    combine_proj_body(bias_in, out, k_up, v_up, m, blockIdx.x, threadIdx.x);
}

__global__ void __launch_bounds__(256)
combine_proj_kv(const float* __restrict__ bk, const float* __restrict__ bv,
                float* __restrict__ k_up, float* __restrict__ v_up)
{
    const int m = 1 + (int)blockIdx.y;
    combine_proj_body((m == 1) ? bk : bv, nullptr, k_up, v_up, m,
                      blockIdx.x, threadIdx.x);
}

// ---------------------------------------------------------------------------
// cp.async helpers
// ---------------------------------------------------------------------------
__device__ __forceinline__ void cp_async16(unsigned int smem_addr, const void* gptr) {
    asm volatile("cp.async.cg.shared.global [%0], [%1], 16;\n"
                 :: "r"(smem_addr), "l"(gptr) : "memory");
}
__device__ __forceinline__ void cp_commit() {
    asm volatile("cp.async.commit_group;\n" ::: "memory");
}
__device__ __forceinline__ void cp_wait1() {
    asm volatile("cp.async.wait_group 1;\n" ::: "memory");
}

// ---------------------------------------------------------------------------
// Split-K fused attention + cache copy — L1tex-byte-optimized.
// Scores: thread owns 2 K rows (lj, lj+32), 8-float kk slice; Q LDS reused
//         across both rows; 8-lane shfl reduce. Ss layout [q][j].
// PV: thread = (js, q-pair, dh-quad); P via LDS.128; V read once per 2 q.
// Mask: int4; softmax vectorized LDS/STS.128.
// ---------------------------------------------------------------------------
__global__ void __launch_bounds__(256, 4)
attn_kernel(const float* __restrict__ cache_k, const float* __restrict__ cache_v,
            const int* __restrict__ mask,
            float* __restrict__ k_up, float* __restrict__ v_up)
{
    const int blk   = blockIdx.x;
    const int bh    = blk >> 3;
    const int split = blk & 7;
    const int b     = bh >> 4;

    __shared__ float Qst[16][68];      // [q][kk] pre-scaled by 1/8
    __shared__ float Vs[2][64][68];    // double-buffered V chunk [j][dh]
    __shared__ float Ss[16][68];       // [q][j] scores -> probabilities
    __shared__ float s_corr[16];
    __shared__ float s_red[128][8];

    const int t = threadIdx.x;

    for (int i = t; i < Qdim * DH; i += 256) {
        const int q  = i >> 6;
        const int kk = i & 63;
        Qst[q][kk] = g_q_heads[(size_t)(bh * Qdim + q) * DH + kk] * 0.125f;
    }

    const int lj = t >> 3;           // 0..31 : K/V rows lj and lj+32
    const int gg = t & 7;            // kk slice: gg*4 and gg*4+32

    const int row = t >> 4;          // softmax role: query row
    const int j4  = (t & 15) * 4;    // softmax role: 4 j's

    const int js  = t >> 7;          // PV: j half
    const int qg  = (t >> 4) & 7;    // PV: query pair
    const int dh4 = t & 15;          // PV: dh quad

    float m_i = -1e30f, l_i = 0.f;
    // acc0,acc1 = query q0 dh[dh4*4..+3]; acc2,acc3 = query q1
    unsigned long long a0 = 0ull, a1 = 0ull, a2 = 0ull, a3 = 0ull;

    const float* Kb = cache_k + (size_t)bh * Cdim * DH;
    const float* Vb = cache_v + (size_t)bh * Cdim * DH;
    float* Kout = k_up + (size_t)bh * KLEN * DH;
    float* Vout = v_up + (size_t)bh * KLEN * DH;
    const int* Mb = mask + (size_t)b * Qdim * KLEN;

    float4 kf[4];    // [row r][slice e]: kf[r*2+e]
    int4 mcur, mnext;
    int cur = 0;

    auto prefetch_k = [&](int c) {
        if (c < 64) {
            const float* p0 = &Kb[((size_t)(c * 64 + lj)) * DH + gg * 4];
            kf[0] = *(const float4*)p0;
            kf[1] = *(const float4*)(p0 + 32);
            const float* p1 = p0 + 32 * DH;
            kf[2] = *(const float4*)p1;
            kf[3] = *(const float4*)(p1 + 32);
        } else {
            const float4 z = make_float4(0.f, 0.f, 0.f, 0.f);
            if (lj < 16) {
                const float* p0 = &Kout[((size_t)(Cdim + lj)) * DH + gg * 4];
                kf[0] = *(const float4*)p0;
                kf[1] = *(const float4*)(p0 + 32);
            } else { kf[0] = z; kf[1] = z; }
            kf[2] = z; kf[3] = z;
        }
    };

    auto prefetch_mask = [&](int c, int4& mr) {
        if (c < 64 || j4 < 16)
            mr = *(const int4*)&Mb[row * KLEN + c * 64 + j4];
        else
            mr = make_int4(0, 0, 0, 0);
    };

    auto issue_v = [&](int c, int buf) {
        if (c < 64) {
            const float* p0 = &Vb[((size_t)(c * 64 + lj)) * DH + gg * 4];
            cp_async16((unsigned int)__cvta_generic_to_shared(&Vs[buf][lj][gg * 4]), p0);
            cp_async16((unsigned int)__cvta_generic_to_shared(&Vs[buf][lj][gg * 4 + 32]), p0 + 32);
            const float* p1 = p0 + 32 * DH;
            cp_async16((unsigned int)__cvta_generic_to_shared(&Vs[buf][lj + 32][gg * 4]), p1);
            cp_async16((unsigned int)__cvta_generic_to_shared(&Vs[buf][lj + 32][gg * 4 + 32]), p1 + 32);
        } else if (c == 64) {
            const float4 z = make_float4(0.f, 0.f, 0.f, 0.f);
            if (lj < 16) {
                const float* p0 = &Vout[((size_t)(Cdim + lj)) * DH + gg * 4];
                cp_async16((unsigned int)__cvta_generic_to_shared(&Vs[buf][lj][gg * 4]), p0);
                cp_async16((unsigned int)__cvta_generic_to_shared(&Vs[buf][lj][gg * 4 + 32]), p0 + 32);
            } else {
                *(float4*)&Vs[buf][lj][gg * 4] = z;
                *(float4*)&Vs[buf][lj][gg * 4 + 32] = z;
            }
            *(float4*)&Vs[buf][lj + 32][gg * 4] = z;
            *(float4*)&Vs[buf][lj + 32][gg * 4 + 32] = z;
        }
        cp_commit();
    };

    prefetch_k(split);
    prefetch_mask(split, mcur);
    issue_v(split, 0);

    for (int c = split; c < 65; c += NSPLIT) {
        const int kvBase = c * 64;
        const bool full  = (c < 64);

        __syncthreads();   // prev PV done; Vs[cur^1] free; Ss writable

        // K cache copy (from registers)
        if (full) {
            float* d0 = &Kout[((size_t)(kvBase + lj)) * DH + gg * 4];
            *(float4*)d0 = kf[0];
            *(float4*)(d0 + 32) = kf[1];
            float* d1 = d0 + 32 * DH;
            *(float4*)d1 = kf[2];
            *(float4*)(d1 + 32) = kf[3];
        }

        // start V load for next chunk into other buffer
        issue_v(c + NSPLIT, cur ^ 1);

        // --- scores: 2 passes of 8 queries, 2 K rows per thread ---
#pragma unroll
        for (int p = 0; p < 2; p++) {
            float s[16];
#pragma unroll
            for (int i = 0; i < 16; i++) s[i] = 0.f;
#pragma unroll
            for (int e = 0; e < 2; e++) {
                const float4 k0 = kf[e];
                const float4 k1 = kf[2 + e];
#pragma unroll
                for (int ql = 0; ql < 8; ql++) {
                    float4 qv = *(const float4*)&Qst[p * 8 + ql][gg * 4 + e * 32];
                    s[ql * 2 + 0] += qv.x * k0.x + qv.y * k0.y + qv.z * k0.z + qv.w * k0.w;
                    s[ql * 2 + 1] += qv.x * k1.x + qv.y * k1.y + qv.z * k1.z + qv.w * k1.w;
                }
            }
#pragma unroll
            for (int off = 1; off <= 4; off <<= 1)
#pragma unroll
                for (int i = 0; i < 16; i++)
                    s[i] += __shfl_xor_sync(0xffffffffu, s[i], off);
            // lane gg keeps query p*8+gg
            Ss[p * 8 + gg][lj]      = s[gg * 2 + 0];
            Ss[p * 8 + gg][lj + 32] = s[gg * 2 + 1];
        }

        // prefetch K + mask for next chunk
        if (c + NSPLIT < 65) {
            prefetch_k(c + NSPLIT);
            prefetch_mask(c + NSPLIT, mnext);
        }

        __syncthreads();   // Ss scores ready

        // --- online softmax (vectorized) ---
        {
            float4 sv = *(const float4*)&Ss[row][j4];
            if (mcur.x == 0) sv.x = -1e9f;
            if (mcur.y == 0) sv.y = -1e9f;
            if (mcur.z == 0) sv.z = -1e9f;
            if (mcur.w == 0) sv.w = -1e9f;
            float mx = fmaxf(fmaxf(sv.x, sv.y), fmaxf(sv.z, sv.w));
#pragma unroll
            for (int off = 8; off; off >>= 1)
                mx = fmaxf(mx, __shfl_xor_sync(0xffffffffu, mx, off));
            const float m_new = fmaxf(m_i, mx);
            const float corr  = __expf(m_i - m_new);
            float4 pv;
            pv.x = __expf(sv.x - m_new);
            pv.y = __expf(sv.y - m_new);
            pv.z = __expf(sv.z - m_new);
            pv.w = __expf(sv.w - m_new);
            *(float4*)&Ss[row][j4] = pv;
            float lsum = pv.x + pv.y + pv.z + pv.w;
#pragma unroll
            for (int off = 8; off; off >>= 1)
                lsum += __shfl_xor_sync(0xffffffffu, lsum, off);
            l_i = l_i * corr + lsum;
            m_i = m_new;
            if ((t & 15) == 0) s_corr[row] = corr;
        }

        cp_wait1();        // current chunk's V resident
        __syncthreads();   // probs + corr + Vs[cur] visible

        // --- uniform V cache copy ---
        if (full) {
            float* d0 = &Vout[((size_t)(kvBase + lj)) * DH + gg * 4];
            *(float4*)d0        = *(const float4*)&Vs[cur][lj][gg * 4];
            *(float4*)(d0 + 32) = *(const float4*)&Vs[cur][lj][gg * 4 + 32];
            float* d1 = d0 + 32 * DH;
            *(float4*)d1        = *(const float4*)&Vs[cur][lj + 32][gg * 4];
            *(float4*)(d1 + 32) = *(const float4*)&Vs[cur][lj + 32][gg * 4 + 32];
        }

        // --- PV: (js, q-pair qg, dh-quad dh4) ---
        {
            const int q0 = qg * 2;
            const float c0 = s_corr[q0];
            const float c1 = s_corr[q0 + 1];
            unsigned long long cc0, cc1;
            asm("mov.b64 %0, {%1, %1};" : "=l"(cc0) : "f"(c0));
            asm("mov.b64 %0, {%1, %1};" : "=l"(cc1) : "f"(c1));
            asm("mul.rn.f32x2 %0, %0, %1;" : "+l"(a0) : "l"(cc0));
            asm("mul.rn.f32x2 %0, %0, %1;" : "+l"(a1) : "l"(cc0));
            asm("mul.rn.f32x2 %0, %0, %1;" : "+l"(a2) : "l"(cc1));
            asm("mul.rn.f32x2 %0, %0, %1;" : "+l"(a3) : "l"(cc1));
            const int jBase = js * 32;
#pragma unroll 4
            for (int j = jBase; j < jBase + 32; j += 4) {
                float4 p0 = *(const float4*)&Ss[q0][j];
                float4 p1 = *(const float4*)&Ss[q0 + 1][j];
                float pa0[4] = {p0.x, p0.y, p0.z, p0.w};
                float pa1[4] = {p1.x, p1.y, p1.z, p1.w};
#pragma unroll
                for (int u = 0; u < 4; u++) {
                    ulonglong2 vv = *reinterpret_cast<const ulonglong2*>(&Vs[cur][j + u][dh4 * 4]);
                    unsigned long long pp0, pp1;
                    asm("mov.b64 %0, {%1, %1};" : "=l"(pp0) : "f"(pa0[u]));
                    asm("mov.b64 %0, {%1, %1};" : "=l"(pp1) : "f"(pa1[u]));
                    asm("fma.rn.f32x2 %0, %1, %2, %0;" : "+l"(a0) : "l"(vv.x), "l"(pp0));
                    asm("fma.rn.f32x2 %0, %1, %2, %0;" : "+l"(a1) : "l"(vv.y), "l"(pp0));
                    asm("fma.rn.f32x2 %0, %1, %2, %0;" : "+l"(a2) : "l"(vv.x), "l"(pp1));
                    asm("fma.rn.f32x2 %0, %1, %2, %0;" : "+l"(a3) : "l"(vv.y), "l"(pp1));
                }
            }
        }

        mcur = mnext;
        cur ^= 1;
    }

    if ((t & 15) == 0)
        g_part_ml[(bh * NSPLIT + split) * Qdim + row] = make_float2(m_i, l_i);

    float f0, f1, f2, f3, f4, f5, f6, f7;
    asm("mov.b64 {%0, %1}, %2;" : "=f"(f0), "=f"(f1) : "l"(a0));
    asm("mov.b64 {%0, %1}, %2;" : "=f"(f2), "=f"(f3) : "l"(a1));
    asm("mov.b64 {%0, %1}, %2;" : "=f"(f4), "=f"(f5) : "l"(a2));
    asm("mov.b64 {%0, %1}, %2;" : "=f"(f6), "=f"(f7) : "l"(a3));

    if (js == 1) {
        float* r = s_red[t - 128];
        r[0] = f0; r[1] = f1; r[2] = f2; r[3] = f3;
        r[4] = f4; r[5] = f5; r[6] = f6; r[7] = f7;
    }
    __syncthreads();
    if (js == 0) {
        const float* r = s_red[t];
        const int q0 = qg * 2;
        const size_t base = ((size_t)(bh * NSPLIT + split) * Qdim) * DH;
        float4 o0 = make_float4(f0 + r[0], f1 + r[1], f2 + r[2], f3 + r[3]);
        float4 o1 = make_float4(f4 + r[4], f5 + r[5], f6 + r[6], f7 + r[7]);
        *(float4*)&g_part_acc[base + (size_t)q0 * DH + dh4 * 4]       = o0;
        *(float4*)&g_part_acc[base + (size_t)(q0 + 1) * DH + dh4 * 4] = o1;
    }
}

// ---------------------------------------------------------------------------
// Combine attention split partials -> g_attn_x
// ---------------------------------------------------------------------------
__global__ void __launch_bounds__(256)
combine_kernel()
{
    const int bh  = blockIdx.x;
    const int t   = threadIdx.x;
    const int row = t >> 4;
    const int dh0 = (t & 15) * 4;

    float2 ml[NSPLIT];
    float m = -1e30f;
#pragma unroll
    for (int s = 0; s < NSPLIT; s++) {
        ml[s] = g_part_ml[(bh * NSPLIT + s) * Qdim + row];
        m = fmaxf(m, ml[s].x);
    }
    float l = 0.f;
    float4 o = make_float4(0.f, 0.f, 0.f, 0.f);
#pragma unroll
    for (int s = 0; s < NSPLIT; s++) {
        const float w = __expf(ml[s].x - m);
        l += ml[s].y * w;
        float4 a = *(const float4*)&g_part_acc[((size_t)(bh * NSPLIT + s) * Qdim + row) * DH + dh0];
        o.x += a.x * w; o.y += a.y * w; o.z += a.z * w; o.w += a.w * w;
    }
    const float inv = 1.f / l;
    const int b = bh >> 4;
    const int h = bh & 15;
    o.x *= inv; o.y *= inv; o.z *= inv; o.w *= inv;
    *(float4*)&g_attn_x[(size_t)(b * Qdim + row) * Ddim + h * DH + dh0] = o;
}

// ---------------------------------------------------------------------------
extern "C" void kernel_launch(void* const* d_in, const int* in_sizes, int n_in,
                              void* d_out, int out_size)
{
    const float* query   = (const float*)d_in[0];
    const float* key     = (const float*)d_in[1];
    const float* value   = (const float*)d_in[2];
    const int*   mask    = (const int*)d_in[3];
    const float* cache_k = (const float*)d_in[4];
    const float* cache_v = (const float*)d_in[5];
    const float* Wq = (const float*)d_in[6];
    const float* bq = (const float*)d_in[7];
    const float* Wk = (const float*)d_in[8];
    const float* bk = (const float*)d_in[9];
    const float* Wv = (const float*)d_in[10];
    const float* bv = (const float*)d_in[11];
    const float* Wo = (const float*)d_in[12];
    const float* bo = (const float*)d_in[13];

    float* out  = (float*)d_out;
    float* k_up = out + (size_t)Bdim * Qdim * Ddim;
    float* v_up = k_up + (size_t)Bdim * Hdim * KLEN * DH;

    // launches 1-3 (attn_kernel is the 4th launch — ncu hits #4)
    proj_kernel<<<dim3(4, 16, 3 * KS), 256>>>(query, key, value, Wq, Wk, Wv, 0);
    combine_proj<<<ROWS, 256>>>(bq, out, k_up, v_up, 0);
    combine_proj_kv<<<dim3(ROWS, 2), 256>>>(bk, bv, k_up, v_up);

    // 4: attention
    attn_kernel<<<Bdim * Hdim * NSPLIT, 256>>>(cache_k, cache_v, mask, k_up, v_up);

    combine_kernel<<<Bdim * Hdim, 256>>>();

    proj_kernel<<<dim3(4, 16, KS), 256>>>(nullptr, nullptr, nullptr, Wo, nullptr, nullptr, 1);
    combine_proj<<<ROWS, 256>>>(bo, out, k_up, v_up, 3);
}

// round 16
// speedup vs baseline: 1.0853x; 1.0844x over previous
#include <cuda_runtime.h>
#include <cstddef>
#include <cstdint>

// ---------------------------------------------------------------------------
// MultiHeadedAttentionWithCache  (B=16,Q=16,D=1024,H=16,DH=64,C=4096,KLEN=4112)
// d_out = concat(out[16,16,1024], k_up[16,16,4112,64], v_up[16,16,4112,64])
// ---------------------------------------------------------------------------

#define Bdim 16
#define Qdim 16
#define Ddim 1024
#define Hdim 16
#define DH   64
#define Cdim 4096
#define KLEN 4112
#define ROWS 256
#define NSPLIT 8
#define KS 4

__device__ float  g_q_heads[ROWS * Ddim];
__device__ float  g_attn_x[ROWS * Ddim];
__device__ float  g_part_acc[256 * NSPLIT * Qdim * DH];
__device__ float2 g_part_ml[256 * NSPLIT * Qdim];
__device__ float  g_proj_part[3 * KS * ROWS * Ddim];

// ---------------------------------------------------------------------------
// Projection GEMM, split-K
// ---------------------------------------------------------------------------
#define BM 64
#define BN 64
#define BK 16

__global__ void __launch_bounds__(256)
proj_kernel(const float* __restrict__ Aq, const float* __restrict__ Ak,
            const float* __restrict__ Av,
            const float* __restrict__ Wq, const float* __restrict__ Wk,
            const float* __restrict__ Wv,
            int mode_base)
{
    const int zz = blockIdx.z;
    const int m  = mode_base ? 3 : (zz / KS);
    const int ks = mode_base ? zz : (zz % KS);
    const int mslot = (m == 3) ? 0 : m;

    const float* A = (m == 0) ? Aq : (m == 1) ? Ak : (m == 2) ? Av : g_attn_x;
    const float* W = (m == 1) ? Wk : (m == 2) ? Wv : Wq;

    __shared__ float As[BK][BM + 4];
    __shared__ float Bs[BK][BN];

    const int rowBase = blockIdx.x * BM;
    const int colBase = blockIdx.y * BN;

    const int t  = threadIdx.x;
    const int tx = t & 15;
    const int ty = t >> 4;

    float acc[4][4];
#pragma unroll
    for (int i = 0; i < 4; i++)
#pragma unroll
        for (int j = 0; j < 4; j++) acc[i][j] = 0.f;

    const int la_r  = t & 63;
    const int la_k4 = (t >> 6) * 4;
    const int lb_k  = t >> 4;
    const int lb_c4 = (t & 15) * 4;

    const int k0 = ks * (Ddim / KS);

    for (int kt = k0; kt < k0 + Ddim / KS; kt += BK) {
        float4 a4 = *(const float4*)&A[(size_t)(rowBase + la_r) * Ddim + kt + la_k4];
        As[la_k4 + 0][la_r] = a4.x;
        As[la_k4 + 1][la_r] = a4.y;
        As[la_k4 + 2][la_r] = a4.z;
        As[la_k4 + 3][la_r] = a4.w;
        *(float4*)&Bs[lb_k][lb_c4] =
            *(const float4*)&W[(size_t)(kt + lb_k) * Ddim + colBase + lb_c4];
        __syncthreads();
#pragma unroll
        for (int kk = 0; kk < BK; kk++) {
            float ar[4], br[4];
            *(float4*)ar = *(const float4*)&As[kk][ty * 4];
            *(float4*)br = *(const float4*)&Bs[kk][tx * 4];
#pragma unroll
            for (int i = 0; i < 4; i++)
#pragma unroll
                for (int j = 0; j < 4; j++)
                    acc[i][j] += ar[i] * br[j];
        }
        __syncthreads();
    }

    float* P = g_proj_part + (size_t)(mslot * KS + ks) * ROWS * Ddim;
#pragma unroll
    for (int i = 0; i < 4; i++) {
        const int row = rowBase + ty * 4 + i;
        float4 v = make_float4(acc[i][0], acc[i][1], acc[i][2], acc[i][3]);
        *(float4*)&P[(size_t)row * Ddim + colBase + tx * 4] = v;
    }
}

// ---------------------------------------------------------------------------
// Combine split-K proj partials + bias + scatter
// ---------------------------------------------------------------------------
__device__ __forceinline__ void combine_proj_body(
    const float* __restrict__ bias_in,
    float* __restrict__ out,
    float* __restrict__ k_up, float* __restrict__ v_up,
    int m, int row, int t)
{
    const int mslot = (m == 3) ? 0 : m;
    const int col = t * 4;

    const float* P = g_proj_part + (size_t)(mslot * KS) * ROWS * Ddim
                   + (size_t)row * Ddim + col;
    float4 s = *(const float4*)&P[0];
#pragma unroll
    for (int ksl = 1; ksl < KS; ksl++) {
        float4 p = *(const float4*)&P[(size_t)ksl * ROWS * Ddim];
        s.x += p.x; s.y += p.y; s.z += p.z; s.w += p.w;
    }
    float4 bb = *(const float4*)&bias_in[col];
    s.x += bb.x; s.y += bb.y; s.z += bb.z; s.w += bb.w;

    const int b  = row >> 4;
    const int qi = row & 15;
    const int h  = col >> 6;
    const int dh = col & 63;

    if (m == 0) {
        *(float4*)&g_q_heads[(size_t)((b * Hdim + h) * Qdim + qi) * DH + dh] = s;
    } else if (m == 1) {
        *(float4*)&k_up[((size_t)(b * Hdim + h) * KLEN + Cdim + qi) * DH + dh] = s;
    } else if (m == 2) {
        *(float4*)&v_up[((size_t)(b * Hdim + h) * KLEN + Cdim + qi) * DH + dh] = s;
    } else {
        *(float4*)&out[(size_t)row * Ddim + col] = s;
    }
}

__global__ void __launch_bounds__(256)
combine_proj(const float* __restrict__ bias_in,
             float* __restrict__ out,
             float* __restrict__ k_up, float* __restrict__ v_up,
             int m)
{
    combine_proj_body(bias_in, out, k_up, v_up, m, blockIdx.x, threadIdx.x);
}

__global__ void __launch_bounds__(256)
combine_proj_kv(const float* __restrict__ bk, const float* __restrict__ bv,
                float* __restrict__ k_up, float* __restrict__ v_up)
{
    const int m = 1 + (int)blockIdx.y;
    combine_proj_body((m == 1) ? bk : bv, nullptr, k_up, v_up, m,
                      blockIdx.x, threadIdx.x);
}

// ---------------------------------------------------------------------------
// cp.async helpers
// ---------------------------------------------------------------------------
__device__ __forceinline__ void cp_async16(unsigned int smem_addr, const void* gptr) {
    asm volatile("cp.async.cg.shared.global [%0], [%1], 16;\n"
                 :: "r"(smem_addr), "l"(gptr) : "memory");
}
__device__ __forceinline__ void cp_commit() {
    asm volatile("cp.async.commit_group;\n" ::: "memory");
}
__device__ __forceinline__ void cp_wait1() {
    asm volatile("cp.async.wait_group 1;\n" ::: "memory");
}

// ---------------------------------------------------------------------------
// Split-K fused attention + cache copy — L1tex-byte-optimized v2.
// Scores: thread owns 2 K rows (lj, lj+32), 8-float kk slice.
// PV: thread = (js j-quarter, qg q-quad, dh4); each 16B V LDS feeds 4 queries.
// Final 4-way js-combine reuses the Vs buffer as scratch.
// ---------------------------------------------------------------------------
__global__ void __launch_bounds__(256, 3)
attn_kernel(const float* __restrict__ cache_k, const float* __restrict__ cache_v,
            const int* __restrict__ mask,
            float* __restrict__ k_up, float* __restrict__ v_up)
{
    const int blk   = blockIdx.x;
    const int bh    = blk >> 3;
    const int split = blk & 7;
    const int b     = bh >> 4;

    __shared__ float Qst[16][68];      // [q][kk] pre-scaled by 1/8
    __shared__ float Vs[2][64][68];    // double-buffered V chunk [j][dh]
    __shared__ float Ss[16][68];       // [q][j] scores -> probabilities
    __shared__ float s_corr[16];

    const int t = threadIdx.x;

    for (int i = t; i < Qdim * DH; i += 256) {
        const int q  = i >> 6;
        const int kk = i & 63;
        Qst[q][kk] = g_q_heads[(size_t)(bh * Qdim + q) * DH + kk] * 0.125f;
    }

    const int lj = t >> 3;           // 0..31 : K/V rows lj and lj+32
    const int gg = t & 7;            // kk slice: gg*4 and gg*4+32

    const int row = t >> 4;          // softmax role: query row
    const int j4  = (t & 15) * 4;    // softmax role: 4 j's

    const int js  = t >> 6;          // PV: j quarter (0..3) -> 16 j each
    const int qg  = (t >> 4) & 3;    // PV: query quad (0..3)
    const int dh4 = t & 15;          // PV: dh quad

    float m_i = -1e30f, l_i = 0.f;
    // a[qi*2], a[qi*2+1] = query qg*4+qi, dh floats dh4*4..dh4*4+3
    unsigned long long a[8];
#pragma unroll
    for (int i = 0; i < 8; i++) a[i] = 0ull;

    const float* Kb = cache_k + (size_t)bh * Cdim * DH;
    const float* Vb = cache_v + (size_t)bh * Cdim * DH;
    float* Kout = k_up + (size_t)bh * KLEN * DH;
    float* Vout = v_up + (size_t)bh * KLEN * DH;
    const int* Mb = mask + (size_t)b * Qdim * KLEN;

    float4 kf[4];    // [row r][slice e]: kf[r*2+e]
    int4 mcur, mnext;
    int cur = 0;

    auto prefetch_k = [&](int c) {
        if (c < 64) {
            const float* p0 = &Kb[((size_t)(c * 64 + lj)) * DH + gg * 4];
            kf[0] = *(const float4*)p0;
            kf[1] = *(const float4*)(p0 + 32);
            const float* p1 = p0 + 32 * DH;
            kf[2] = *(const float4*)p1;
            kf[3] = *(const float4*)(p1 + 32);
        } else {
            const float4 z = make_float4(0.f, 0.f, 0.f, 0.f);
            if (lj < 16) {
                const float* p0 = &Kout[((size_t)(Cdim + lj)) * DH + gg * 4];
                kf[0] = *(const float4*)p0;
                kf[1] = *(const float4*)(p0 + 32);
            } else { kf[0] = z; kf[1] = z; }
            kf[2] = z; kf[3] = z;
        }
    };

    auto prefetch_mask = [&](int c, int4& mr) {
        if (c < 64 || j4 < 16)
            mr = *(const int4*)&Mb[row * KLEN + c * 64 + j4];
        else
            mr = make_int4(0, 0, 0, 0);
    };

    auto issue_v = [&](int c, int buf) {
        if (c < 64) {
            const float* p0 = &Vb[((size_t)(c * 64 + lj)) * DH + gg * 4];
            cp_async16((unsigned int)__cvta_generic_to_shared(&Vs[buf][lj][gg * 4]), p0);
            cp_async16((unsigned int)__cvta_generic_to_shared(&Vs[buf][lj][gg * 4 + 32]), p0 + 32);
            const float* p1 = p0 + 32 * DH;
            cp_async16((unsigned int)__cvta_generic_to_shared(&Vs[buf][lj + 32][gg * 4]), p1);
            cp_async16((unsigned int)__cvta_generic_to_shared(&Vs[buf][lj + 32][gg * 4 + 32]), p1 + 32);
        } else if (c == 64) {
            const float4 z = make_float4(0.f, 0.f, 0.f, 0.f);
            if (lj < 16) {
                const float* p0 = &Vout[((size_t)(Cdim + lj)) * DH + gg * 4];
                cp_async16((unsigned int)__cvta_generic_to_shared(&Vs[buf][lj][gg * 4]), p0);
                cp_async16((unsigned int)__cvta_generic_to_shared(&Vs[buf][lj][gg * 4 + 32]), p0 + 32);
            } else {
                *(float4*)&Vs[buf][lj][gg * 4] = z;
                *(float4*)&Vs[buf][lj][gg * 4 + 32] = z;
            }
            *(float4*)&Vs[buf][lj + 32][gg * 4] = z;
            *(float4*)&Vs[buf][lj + 32][gg * 4 + 32] = z;
        }
        cp_commit();
    };

    prefetch_k(split);
    prefetch_mask(split, mcur);
    issue_v(split, 0);

    for (int c = split; c < 65; c += NSPLIT) {
        const int kvBase = c * 64;
        const bool full  = (c < 64);

        __syncthreads();   // prev PV done; Vs[cur^1] free; Ss writable

        // K cache copy (from registers)
        if (full) {
            float* d0 = &Kout[((size_t)(kvBase + lj)) * DH + gg * 4];
            *(float4*)d0 = kf[0];
            *(float4*)(d0 + 32) = kf[1];
            float* d1 = d0 + 32 * DH;
            *(float4*)d1 = kf[2];
            *(float4*)(d1 + 32) = kf[3];
        }

        // start V load for next chunk into other buffer
        issue_v(c + NSPLIT, cur ^ 1);

        // --- scores: 2 passes of 8 queries, 2 K rows per thread ---
#pragma unroll
        for (int p = 0; p < 2; p++) {
            float s[16];
#pragma unroll
            for (int i = 0; i < 16; i++) s[i] = 0.f;
#pragma unroll
            for (int e = 0; e < 2; e++) {
                const float4 k0 = kf[e];
                const float4 k1 = kf[2 + e];
#pragma unroll
                for (int ql = 0; ql < 8; ql++) {
                    float4 qv = *(const float4*)&Qst[p * 8 + ql][gg * 4 + e * 32];
                    s[ql * 2 + 0] += qv.x * k0.x + qv.y * k0.y + qv.z * k0.z + qv.w * k0.w;
                    s[ql * 2 + 1] += qv.x * k1.x + qv.y * k1.y + qv.z * k1.z + qv.w * k1.w;
                }
            }
#pragma unroll
            for (int off = 1; off <= 4; off <<= 1)
#pragma unroll
                for (int i = 0; i < 16; i++)
                    s[i] += __shfl_xor_sync(0xffffffffu, s[i], off);
            // lane gg keeps query p*8+gg
            Ss[p * 8 + gg][lj]      = s[gg * 2 + 0];
            Ss[p * 8 + gg][lj + 32] = s[gg * 2 + 1];
        }

        // prefetch K + mask for next chunk
        if (c + NSPLIT < 65) {
            prefetch_k(c + NSPLIT);
            prefetch_mask(c + NSPLIT, mnext);
        }

        __syncthreads();   // Ss scores ready

        // --- online softmax (vectorized) ---
        {
            float4 sv = *(const float4*)&Ss[row][j4];
            if (mcur.x == 0) sv.x = -1e9f;
            if (mcur.y == 0) sv.y = -1e9f;
            if (mcur.z == 0) sv.z = -1e9f;
            if (mcur.w == 0) sv.w = -1e9f;
            float mx = fmaxf(fmaxf(sv.x, sv.y), fmaxf(sv.z, sv.w));
#pragma unroll
            for (int off = 8; off; off >>= 1)
                mx = fmaxf(mx, __shfl_xor_sync(0xffffffffu, mx, off));
            const float m_new = fmaxf(m_i, mx);
            const float corr  = __expf(m_i - m_new);
            float4 pv;
            pv.x = __expf(sv.x - m_new);
            pv.y = __expf(sv.y - m_new);
            pv.z = __expf(sv.z - m_new);
            pv.w = __expf(sv.w - m_new);
            *(float4*)&Ss[row][j4] = pv;
            float lsum = pv.x + pv.y + pv.z + pv.w;
#pragma unroll
            for (int off = 8; off; off >>= 1)
                lsum += __shfl_xor_sync(0xffffffffu, lsum, off);
            l_i = l_i * corr + lsum;
            m_i = m_new;
            if ((t & 15) == 0) s_corr[row] = corr;
        }

        cp_wait1();        // current chunk's V resident
        __syncthreads();   // probs + corr + Vs[cur] visible

        // --- uniform V cache copy ---
        if (full) {
            float* d0 = &Vout[((size_t)(kvBase + lj)) * DH + gg * 4];
            *(float4*)d0        = *(const float4*)&Vs[cur][lj][gg * 4];
            *(float4*)(d0 + 32) = *(const float4*)&Vs[cur][lj][gg * 4 + 32];
            float* d1 = d0 + 32 * DH;
            *(float4*)d1        = *(const float4*)&Vs[cur][lj + 32][gg * 4];
            *(float4*)(d1 + 32) = *(const float4*)&Vs[cur][lj + 32][gg * 4 + 32];
        }

        // --- PV: (js j-quarter, qg q-quad, dh4) — 4 queries per V read ---
        {
            const int q0 = qg * 4;
#pragma unroll
            for (int qi = 0; qi < 4; qi++) {
                unsigned long long cc;
                const float cv = s_corr[q0 + qi];
                asm("mov.b64 %0, {%1, %1};" : "=l"(cc) : "f"(cv));
                asm("mul.rn.f32x2 %0, %0, %1;" : "+l"(a[qi * 2])     : "l"(cc));
                asm("mul.rn.f32x2 %0, %0, %1;" : "+l"(a[qi * 2 + 1]) : "l"(cc));
            }
            const int jBase = js * 16;
#pragma unroll
            for (int i4 = 0; i4 < 16; i4 += 4) {
                const int j = jBase + i4;
                float pa[4][4];
#pragma unroll
                for (int qi = 0; qi < 4; qi++) {
                    float4 p = *(const float4*)&Ss[q0 + qi][j];
                    pa[qi][0] = p.x; pa[qi][1] = p.y; pa[qi][2] = p.z; pa[qi][3] = p.w;
                }
#pragma unroll
                for (int u = 0; u < 4; u++) {
                    ulonglong2 vv = *reinterpret_cast<const ulonglong2*>(&Vs[cur][j + u][dh4 * 4]);
#pragma unroll
                    for (int qi = 0; qi < 4; qi++) {
                        unsigned long long pp;
                        asm("mov.b64 %0, {%1, %1};" : "=l"(pp) : "f"(pa[qi][u]));
                        asm("fma.rn.f32x2 %0, %1, %2, %0;" : "+l"(a[qi * 2])     : "l"(vv.x), "l"(pp));
                        asm("fma.rn.f32x2 %0, %1, %2, %0;" : "+l"(a[qi * 2 + 1]) : "l"(vv.y), "l"(pp));
                    }
                }
            }
        }

        mcur = mnext;
        cur ^= 1;
    }

    if ((t & 15) == 0)
        g_part_ml[(bh * NSPLIT + split) * Qdim + row] = make_float2(m_i, l_i);

    // unpack accumulators: f[qi][4]
    float f[4][4];
#pragma unroll
    for (int qi = 0; qi < 4; qi++) {
        asm("mov.b64 {%0, %1}, %2;" : "=f"(f[qi][0]), "=f"(f[qi][1]) : "l"(a[qi * 2]));
        asm("mov.b64 {%0, %1}, %2;" : "=f"(f[qi][2]), "=f"(f[qi][3]) : "l"(a[qi * 2 + 1]));
    }

    // 4-way js combine using Vs as scratch (dead after last PV)
    float* red = &Vs[0][0][0];   // need 192*16 floats = 3072 <= 8704
    __syncthreads();
    if (js > 0) {
        float* r = red + ((size_t)(js - 1) * 64 + qg * 16 + dh4) * 16;
#pragma unroll
        for (int qi = 0; qi < 4; qi++)
            *(float4*)&r[qi * 4] = make_float4(f[qi][0], f[qi][1], f[qi][2], f[qi][3]);
    }
    __syncthreads();
    if (js == 0) {
#pragma unroll
        for (int k = 0; k < 3; k++) {
            const float* r = red + ((size_t)k * 64 + qg * 16 + dh4) * 16;
#pragma unroll
            for (int qi = 0; qi < 4; qi++) {
                float4 p = *(const float4*)&r[qi * 4];
                f[qi][0] += p.x; f[qi][1] += p.y; f[qi][2] += p.z; f[qi][3] += p.w;
            }
        }
        const int q0 = qg * 4;
        const size_t base = ((size_t)(bh * NSPLIT + split) * Qdim) * DH;
#pragma unroll
        for (int qi = 0; qi < 4; qi++) {
            float4 o = make_float4(f[qi][0], f[qi][1], f[qi][2], f[qi][3]);
            *(float4*)&g_part_acc[base + (size_t)(q0 + qi) * DH + dh4 * 4] = o;
        }
    }
}

// ---------------------------------------------------------------------------
// Combine attention split partials -> g_attn_x
// ---------------------------------------------------------------------------
__global__ void __launch_bounds__(256)
combine_kernel()
{
    const int bh  = blockIdx.x;
    const int t   = threadIdx.x;
    const int row = t >> 4;
    const int dh0 = (t & 15) * 4;

    float2 ml[NSPLIT];
    float m = -1e30f;
#pragma unroll
    for (int s = 0; s < NSPLIT; s++) {
        ml[s] = g_part_ml[(bh * NSPLIT + s) * Qdim + row];
        m = fmaxf(m, ml[s].x);
    }
    float l = 0.f;
    float4 o = make_float4(0.f, 0.f, 0.f, 0.f);
#pragma unroll
    for (int s = 0; s < NSPLIT; s++) {
        const float w = __expf(ml[s].x - m);
        l += ml[s].y * w;
        float4 a = *(const float4*)&g_part_acc[((size_t)(bh * NSPLIT + s) * Qdim + row) * DH + dh0];
        o.x += a.x * w; o.y += a.y * w; o.z += a.z * w; o.w += a.w * w;
    }
    const float inv = 1.f / l;
    const int b = bh >> 4;
    const int h = bh & 15;
    o.x *= inv; o.y *= inv; o.z *= inv; o.w *= inv;
    *(float4*)&g_attn_x[(size_t)(b * Qdim + row) * Ddim + h * DH + dh0] = o;
}

// ---------------------------------------------------------------------------
extern "C" void kernel_launch(void* const* d_in, const int* in_sizes, int n_in,
                              void* d_out, int out_size)
{
    const float* query   = (const float*)d_in[0];
    const float* key     = (const float*)d_in[1];
    const float* value   = (const float*)d_in[2];
    const int*   mask    = (const int*)d_in[3];
    const float* cache_k = (const float*)d_in[4];
    const float* cache_v = (const float*)d_in[5];
    const float* Wq = (const float*)d_in[6];
    const float* bq = (const float*)d_in[7];
    const float* Wk = (const float*)d_in[8];
    const float* bk = (const float*)d_in[9];
    const float* Wv = (const float*)d_in[10];
    const float* bv = (const float*)d_in[11];
    const float* Wo = (const float*)d_in[12];
    const float* bo = (const float*)d_in[13];

    float* out  = (float*)d_out;
    float* k_up = out + (size_t)Bdim * Qdim * Ddim;
    float* v_up = k_up + (size_t)Bdim * Hdim * KLEN * DH;

    // launches 1-3 (attn_kernel is the 4th launch — ncu hits #4)
    proj_kernel<<<dim3(4, 16, 3 * KS), 256>>>(query, key, value, Wq, Wk, Wv, 0);
    combine_proj<<<ROWS, 256>>>(bq, out, k_up, v_up, 0);
    combine_proj_kv<<<dim3(ROWS, 2), 256>>>(bk, bv, k_up, v_up);

    // 4: attention
    attn_kernel<<<Bdim * Hdim * NSPLIT, 256>>>(cache_k, cache_v, mask, k_up, v_up);

    combine_kernel<<<Bdim * Hdim, 256>>>();

    proj_kernel<<<dim3(4, 16, KS), 256>>>(nullptr, nullptr, nullptr, Wo, nullptr, nullptr, 1);
    combine_proj<<<ROWS, 256>>>(bo, out, k_up, v_up, 3);
}